// round 14
// baseline (speedup 1.0000x reference)
#include <cuda_runtime.h>
#include <math.h>
#include <cstdint>

// Fixed shapes: z_i, z_j are [4096, 128] fp32
#define D       128
#define BHALF   4096
#define NROWS   8192
#define NT      64
#define NPAIRS  (NT * (NT + 1) / 2)   // 2080 triangular 128x128 tiles

// Scratch (__device__ globals; no allocation allowed)
__device__ uint8_t g_q8[NROWS * D];   // 16 * normalized rows, e4m3 (1 MB, L2)
__device__ float g_S[NROWS];          // per-row sum of exp(sim), self excluded
__device__ float g_pos[NROWS];        // per-row positive logit

// ---------------------------------------------------------------------------
__device__ __forceinline__ uint32_t smem_u32(const void* p) {
    uint32_t a;
    asm("{ .reg .u64 t; cvta.to.shared.u64 t, %1; cvt.u32.u64 %0, t; }"
        : "=r"(a) : "l"(p));
    return a;
}
__device__ __forceinline__ void ldmatrix_x4(uint32_t* r, uint32_t a) {
    asm volatile("ldmatrix.sync.aligned.m8n8.x4.shared.b16 {%0,%1,%2,%3}, [%4];"
                 : "=r"(r[0]), "=r"(r[1]), "=r"(r[2]), "=r"(r[3]) : "r"(a));
}
__device__ __forceinline__ void ldmatrix_x2(uint32_t* r, uint32_t a) {
    asm volatile("ldmatrix.sync.aligned.m8n8.x2.shared.b16 {%0,%1}, [%2];"
                 : "=r"(r[0]), "=r"(r[1]) : "r"(a));
}
// D[16x8] += A[16x32] * B[8x32]^T, e4m3 inputs, fp32 accumulate (QMMA)
__device__ __forceinline__ void mma_fp8(float* c, const uint32_t* a,
                                        const uint32_t* b) {
    asm volatile(
        "mma.sync.aligned.m16n8k32.row.col.f32.e4m3.e4m3.f32 "
        "{%0,%1,%2,%3}, {%4,%5,%6,%7}, {%8,%9}, {%0,%1,%2,%3};"
        : "+f"(c[0]), "+f"(c[1]), "+f"(c[2]), "+f"(c[3])
        : "r"(a[0]), "r"(a[1]), "r"(a[2]), "r"(a[3]), "r"(b[0]), "r"(b[1]));
}
__device__ __forceinline__ uint16_t pack_e4m3x2(float hi, float lo) {
    uint16_t r;
    asm("cvt.rn.satfinite.e4m3x2.f32 %0, %1, %2;" : "=h"(r) : "f"(hi), "f"(lo));
    return r;
}
#define CP_ASYNC16(dst, src) \
    asm volatile("cp.async.cg.shared.global [%0], [%1], 16;" \
                 :: "r"(dst), "l"(src) : "memory")
#define CP_COMMIT() asm volatile("cp.async.commit_group;" ::: "memory")
#define CP_WAIT0()  asm volatile("cp.async.wait_group 0;" ::: "memory")

// ---------------------------------------------------------------------------
// Kernel 1: row L2-normalize (1e-8 clamp), scale by 16, quantize to e4m3.
// One warp per row; each lane converts 4 elements -> one uint32 store.
// Also zeroes g_S and d_out for this replay.
// ---------------------------------------------------------------------------
__global__ __launch_bounds__(256)
void k_normalize(const float* __restrict__ zi, const float* __restrict__ zj,
                 float* __restrict__ out) {
    const int row  = (blockIdx.x << 3) + (threadIdx.x >> 5);
    const int lane = threadIdx.x & 31;
    const float* src = (row < BHALF) ? (zi + (size_t)row * D)
                                     : (zj + (size_t)(row - BHALF) * D);
    float4 v = reinterpret_cast<const float4*>(src)[lane];
    float ss = v.x * v.x + v.y * v.y + v.z * v.z + v.w * v.w;
    #pragma unroll
    for (int o = 16; o > 0; o >>= 1) ss += __shfl_xor_sync(0xffffffffu, ss, o);
    const float inv = 16.0f / fmaxf(sqrtf(ss), 1e-8f);   // power-of-2 scale

    const uint16_t p0 = pack_e4m3x2(v.y * inv, v.x * inv);  // bytes [x, y]
    const uint16_t p1 = pack_e4m3x2(v.w * inv, v.z * inv);  // bytes [z, w]
    reinterpret_cast<uint32_t*>(g_q8 + (size_t)row * D)[lane] =
        (uint32_t)p0 | ((uint32_t)p1 << 16);

    if (lane == 0) g_S[row] = 0.0f;
    if (row == 0 && lane == 0) out[0] = 0.0f;   // re-zero every replay
}

// ---------------------------------------------------------------------------
// Kernel 2: triangular (tj >= ti) 128x128 tiles via fp8 mma.sync (QMMA, 2x the
// bf16 legacy rate). 8 warps; warp (wr,wc) owns 64x32 = 4x4 m16n8 fragments.
// Full K=128 staged via cp.async: 16 KB per matrix (128 rows x 128 B),
// XOR-swizzled rows -> conflict-free ldmatrix. acc = sum q_i q_j = 256*cos,
// so sim = cos/0.5 = acc/128.
// Epilogue: exp(sim); row sums always; column sums (transpose contribution)
// for off-diagonal tiles; positives write both g_pos[gi] and mirror g_pos[gj].
// ---------------------------------------------------------------------------
__global__ __launch_bounds__(256, 2)
void k_sim() {
    __shared__ __align__(16) uint8_t sA[128 * 128];
    __shared__ __align__(16) uint8_t sB[128 * 128];

    const int tid  = threadIdx.x;
    const int wid  = tid >> 5;
    const int lane = tid & 31;

    // Triangular decode
    int ti = 0, tj;
    {
        int rem = blockIdx.x, rowlen = NT;
        while (rem >= rowlen) { rem -= rowlen; rowlen--; ti++; }
        tj = ti + rem;
    }
    const int I0 = ti * 128, J0 = tj * 128;
    const bool diag = (ti == tj);

    const int wr = wid >> 2;          // 0..1 : 64-row block
    const int wc = wid & 3;           // 0..3 : 32-col block
    const uint32_t sa = smem_u32(sA), sb = smem_u32(sB);

    // ldmatrix lane->tile assignment (byte-identical geometry to the bf16 ver:
    // one 16B chunk now carries k=16 fp8; one mma step consumes 2 chunks = k32)
    const int a_row = wr * 64 + ((lane >> 3) & 1) * 8 + (lane & 7);
    const int a_cb  = lane >> 4;                 // k-subchunk: 0 -> k0-15, 1 -> k16-31
    const int b_row = wc * 32 + (lane & 7);
    const int b_cb  = (lane >> 3) & 1;
    const int a_swz = a_row & 7;
    const int b_swz = b_row & 7;

    // ---- Stage full K=128 for A and B: 1024 16B chunks each, 4/thread ----
    #pragma unroll
    for (int i = 0; i < 4; i++) {
        const int e = tid + 256 * i;             // 0..1023
        const int r = e >> 3, c = e & 7;         // row, 16B chunk
        const uint32_t off = (uint32_t)r * 128u + (uint32_t)((c ^ (r & 7)) << 4);
        CP_ASYNC16(sa + off, (const void*)(g_q8 + (size_t)(I0 + r) * D + c * 16));
        CP_ASYNC16(sb + off, (const void*)(g_q8 + (size_t)(J0 + r) * D + c * 16));
    }
    CP_COMMIT();

    float acc[4][4][4];
    #pragma unroll
    for (int mi = 0; mi < 4; mi++)
        #pragma unroll
        for (int ni = 0; ni < 4; ni++)
            #pragma unroll
            for (int f = 0; f < 4; f++) acc[mi][ni][f] = 0.0f;

    CP_WAIT0();
    __syncthreads();

    // ---- Main loop: 4 chunks of k=32 ----
    #pragma unroll
    for (int kc = 0; kc < 4; kc++) {
        uint32_t af[4][4], bf[4][2];
        #pragma unroll
        for (int mi = 0; mi < 4; mi++) {
            const uint32_t addr = sa + (uint32_t)(a_row + mi * 16) * 128u
                + (uint32_t)(((kc * 2 + a_cb) ^ a_swz) << 4);
            ldmatrix_x4(af[mi], addr);
        }
        #pragma unroll
        for (int ni = 0; ni < 4; ni++) {
            const uint32_t addr = sb + (uint32_t)(b_row + ni * 8) * 128u
                + (uint32_t)(((kc * 2 + b_cb) ^ b_swz) << 4);
            ldmatrix_x2(bf[ni], addr);
        }
        #pragma unroll
        for (int mi = 0; mi < 4; mi++)
            #pragma unroll
            for (int ni = 0; ni < 4; ni++)
                mma_fp8(acc[mi][ni], af[mi], bf[ni]);
    }

    // ---- Epilogue ----
    // c-frag: c0:(trow, tcol2) c1:(trow, tcol2+1) c2:(trow+8, .) c3:(trow+8, .+1)
    const int trow  = lane >> 2;
    const int tcol2 = (lane & 3) * 2;
    const float SC  = 0.0078125f;     // sim = acc / 128

    float cs[4][2];                   // column sums over this thread's 8 rows
    #pragma unroll
    for (int ni = 0; ni < 4; ni++) { cs[ni][0] = 0.0f; cs[ni][1] = 0.0f; }

    #pragma unroll
    for (int mi = 0; mi < 4; mi++) {
        const int gi0 = I0 + wr * 64 + mi * 16 + trow;
        const int gi1 = gi0 + 8;
        const int p0 = gi0 ^ BHALF, p1 = gi1 ^ BHALF;
        float rs0 = 0.0f, rs1 = 0.0f;
        #pragma unroll
        for (int ni = 0; ni < 4; ni++) {
            const int gj = J0 + wc * 32 + ni * 8 + tcol2;
            const float* c = acc[mi][ni];
            float s0 = c[0] * SC, s1 = c[1] * SC;
            float s2 = c[2] * SC, s3 = c[3] * SC;
            float e0 = __expf(s0), e1 = __expf(s1);
            float e2 = __expf(s2), e3 = __expf(s3);
            if (diag) {                                  // mask self-similarity
                if (gj     == gi0) e0 = 0.0f;
                if (gj + 1 == gi0) e1 = 0.0f;
                if (gj     == gi1) e2 = 0.0f;
                if (gj + 1 == gi1) e3 = 0.0f;
            }
            if (gj     == p0) { g_pos[gi0] = s0; g_pos[gj]     = s0; }
            if (gj + 1 == p0) { g_pos[gi0] = s1; g_pos[gj + 1] = s1; }
            if (gj     == p1) { g_pos[gi1] = s2; g_pos[gj]     = s2; }
            if (gj + 1 == p1) { g_pos[gi1] = s3; g_pos[gj + 1] = s3; }
            rs0 += e0 + e1;
            rs1 += e2 + e3;
            cs[ni][0] += e0 + e2;     // transpose (column) contribution
            cs[ni][1] += e1 + e3;
        }
        rs0 += __shfl_xor_sync(0xffffffffu, rs0, 1);
        rs0 += __shfl_xor_sync(0xffffffffu, rs0, 2);
        rs1 += __shfl_xor_sync(0xffffffffu, rs1, 1);
        rs1 += __shfl_xor_sync(0xffffffffu, rs1, 2);
        if ((lane & 3) == 0) {
            atomicAdd(&g_S[gi0], rs0);
            atomicAdd(&g_S[gi1], rs1);
        }
    }

    if (!diag) {
        #pragma unroll
        for (int ni = 0; ni < 4; ni++) {
            float c0 = cs[ni][0], c1 = cs[ni][1];
            #pragma unroll
            for (int o = 4; o < 32; o <<= 1) {
                c0 += __shfl_xor_sync(0xffffffffu, c0, o);
                c1 += __shfl_xor_sync(0xffffffffu, c1, o);
            }
            if (lane < 4) {
                const int gj = J0 + wc * 32 + ni * 8 + lane * 2;
                atomicAdd(&g_S[gj],     c0);
                atomicAdd(&g_S[gj + 1], c1);
            }
        }
    }
}

// ---------------------------------------------------------------------------
// Kernel 3: loss = mean(log(S_i) - pos_i), 32 blocks + atomic accumulate.
// ---------------------------------------------------------------------------
__global__ __launch_bounds__(256)
void k_final(float* __restrict__ out) {
    const int i = blockIdx.x * 256 + threadIdx.x;   // exactly 8192 threads
    float acc = logf(g_S[i]) - g_pos[i];
    #pragma unroll
    for (int o = 16; o > 0; o >>= 1)
        acc += __shfl_down_sync(0xffffffffu, acc, o);
    __shared__ float ws[8];
    if ((threadIdx.x & 31) == 0) ws[threadIdx.x >> 5] = acc;
    __syncthreads();
    if (threadIdx.x == 0) {
        float tot = 0.0f;
        #pragma unroll
        for (int w = 0; w < 8; w++) tot += ws[w];
        atomicAdd(out, tot * (1.0f / (float)NROWS));
    }
}

// ---------------------------------------------------------------------------
extern "C" void kernel_launch(void* const* d_in, const int* in_sizes, int n_in,
                              void* d_out, int out_size) {
    (void)in_sizes; (void)n_in; (void)out_size;
    const float* zi = (const float*)d_in[0];
    const float* zj = (const float*)d_in[1];
    float* out = (float*)d_out;

    k_normalize<<<NROWS / 8, 256>>>(zi, zj, out);
    k_sim<<<NPAIRS, 256>>>();
    k_final<<<NROWS / 256, 256>>>(out);
}